// round 11
// baseline (speedup 1.0000x reference)
#include <cuda_runtime.h>

#define NB 256
#define NT 1024
#define NV 5000
#define ND 100
#define NH 64
#define NC 2

// Scratch: EW = E @ W + b, [V, H]. 1.28 MB -> fully L2-resident.
__device__ float g_EWb[NV * NH];

// ---------------------------------------------------------------------------
// Kernel A: EWb[v][j] = sum_d E[v][d] * W[d][j] + b[j]
// ---------------------------------------------------------------------------
__global__ void ew_kernel(const float* __restrict__ E,
                          const float* __restrict__ W,
                          const float* __restrict__ bias) {
    int v = blockIdx.x * 4 + (threadIdx.x >> 6);
    int j = threadIdx.x & 63;
    if (v >= NV) return;
    float acc = bias[j];
    const float* e = E + v * ND;
    #pragma unroll 4
    for (int d = 0; d < ND; d++)
        acc = fmaf(e[d], W[d * NH + j], acc);
    g_EWb[v * NH + j] = acc;
}

// HW tanh (MUFU.TANH): lat 16, single instruction, ~2^-11 error.
__device__ __forceinline__ float tanh_fast(float x) {
    float y;
    asm("tanh.approx.f32 %0, %1;" : "=f"(y) : "f"(x));
    return y;
}

// Named barrier over a 128-thread subset (ids 1..4).
__device__ __forceinline__ void bar_group(int id) {
    asm volatile("bar.sync %0, 128;" :: "r"(id) : "memory");
}

// ---------------------------------------------------------------------------
// Kernel B: masked tanh RNN, T=1024 steps + mean-pool + dense + sigmoid.
// FOUR ROWS PER BLOCK (512 threads = 16 warps = 4 groups x 4 warps), 64
// blocks -> exactly 1 block/SM (regs ~36K block forbids a second), every
// SMSP holds 4 warps from 4 INDEPENDENT recurrences -> the warp scheduler
// interleaves their serial chains (R8 showed compiler-level fusion fails;
// this is scheduler-level, zero register cost). Each group runs the proven
// R4 machinery VERBATIM: K-split by 2 in-warp, lanes (l, l+16) of group-
// warp w own output j = 16w + (l&15), 32 scalar FFMA + 8 LDS.128 per
// thread, one shfl.bfly(16) merge, ptxas-scheduled unroll-2 ping-pong.
// Groups sync on their OWN named barrier (bar.sync 1+g, 128) so they
// drift freely and cover each other's barrier skew and latency stalls.
// ---------------------------------------------------------------------------
__global__ void __launch_bounds__(512) rnn_kernel(
    const int* __restrict__ tokens,
    const float* __restrict__ U,
    const float* __restrict__ Wd,
    const float* __restrict__ bd,
    float* __restrict__ out)
{
    __shared__ __align__(16) float hbuf[4][2][NH];
    __shared__ float red[4][4][2];
    const int g     = threadIdx.x >> 7;        // row group 0..3
    const int gtid  = threadIdx.x & 127;       // tid within group
    const int w     = gtid >> 5;               // warp within group
    const int l     = threadIdx.x & 31;
    const int j     = w * 16 + (l & 15);
    const int kbase = (l >> 4) * 32;
    const bool low  = (l < 16);
    const int barid = 1 + g;
    const int b     = blockIdx.x * 4 + g;      // this group's batch row

    // U[kbase..kbase+31][j] in 32 registers.
    float Ucol[NH / 2];
    #pragma unroll
    for (int k = 0; k < NH / 2; k++)
        Ucol[k] = U[(kbase + k) * NH + j];

    if (gtid < NH) hbuf[g][0][gtid] = 0.f;
    __syncthreads();   // one full-block barrier covers all groups' init

    const int* trow = tokens + b * NT;
    float h = 0.f, s = 0.f;

    // Pipeline: tokens 3 ahead, EW rows 2 ahead (2 steps >= L2 ~234cyc).
    int tok0 = trow[0];
    int tok1 = trow[1];
    int tok2 = trow[2];
    float ew0 = g_EWb[tok0 * NH + j];
    float ew1 = g_EWb[tok1 * NH + j];

    #pragma unroll 2
    for (int t = 0; t < NT; t++) {
        int t3 = (t + 3 < NT) ? (t + 3) : (NT - 1);
        int tok3 = trow[t3];
        float ew2 = g_EWb[tok2 * NH + j];

        // Partial dot: sum_{k in half} h[k] * U[k][j].  8 broadcast LDS.128.
        const float4* hp = reinterpret_cast<const float4*>(hbuf[g][t & 1] + kbase);
        float4 h0 = hp[0], h1 = hp[1], h2 = hp[2], h3 = hp[3];
        float4 h4 = hp[4], h5 = hp[5], h6 = hp[6], h7 = hp[7];
        float a0 = 0.f, a1 = 0.f, a2 = 0.f, a3 = 0.f;
        float a4 = 0.f, a5 = 0.f, a6 = 0.f, a7 = 0.f;
        a0 = fmaf(h0.x, Ucol[0],  a0);  a1 = fmaf(h0.y, Ucol[1],  a1);
        a2 = fmaf(h0.z, Ucol[2],  a2);  a3 = fmaf(h0.w, Ucol[3],  a3);
        a4 = fmaf(h1.x, Ucol[4],  a4);  a5 = fmaf(h1.y, Ucol[5],  a5);
        a6 = fmaf(h1.z, Ucol[6],  a6);  a7 = fmaf(h1.w, Ucol[7],  a7);
        a0 = fmaf(h2.x, Ucol[8],  a0);  a1 = fmaf(h2.y, Ucol[9],  a1);
        a2 = fmaf(h2.z, Ucol[10], a2);  a3 = fmaf(h2.w, Ucol[11], a3);
        a4 = fmaf(h3.x, Ucol[12], a4);  a5 = fmaf(h3.y, Ucol[13], a5);
        a6 = fmaf(h3.z, Ucol[14], a6);  a7 = fmaf(h3.w, Ucol[15], a7);
        a0 = fmaf(h4.x, Ucol[16], a0);  a1 = fmaf(h4.y, Ucol[17], a1);
        a2 = fmaf(h4.z, Ucol[18], a2);  a3 = fmaf(h4.w, Ucol[19], a3);
        a4 = fmaf(h5.x, Ucol[20], a4);  a5 = fmaf(h5.y, Ucol[21], a5);
        a6 = fmaf(h5.z, Ucol[22], a6);  a7 = fmaf(h5.w, Ucol[23], a7);
        a0 = fmaf(h6.x, Ucol[24], a0);  a1 = fmaf(h6.y, Ucol[25], a1);
        a2 = fmaf(h6.z, Ucol[26], a2);  a3 = fmaf(h6.w, Ucol[27], a3);
        a4 = fmaf(h7.x, Ucol[28], a4);  a5 = fmaf(h7.y, Ucol[29], a5);
        a6 = fmaf(h7.z, Ucol[30], a6);  a7 = fmaf(h7.w, Ucol[31], a7);
        float p = ((a0 + a1) + (a2 + a3)) + ((a4 + a5) + (a6 + a7));
        // Merge K-halves: partner lane is l^16, same warp.
        float a = p + __shfl_xor_sync(0xffffffffu, p, 16) + ew0;
        float hn = tanh_fast(a);

        // Masked recurrence: token 0 carries previous state (group-uniform).
        if (tok0 != 0) h = hn;
        s += h;

        // Publish into the other buffer (one writer per output).
        if (low) hbuf[g][(t & 1) ^ 1][j] = h;
        bar_group(barid);

        tok0 = tok1; tok1 = tok2; tok2 = tok3;
        ew0 = ew1;  ew1 = ew2;
    }

    // Epilogue: mean pool -> dense (64 -> 2) -> sigmoid, per group.
    // Output j is held by 2 lanes; count only l<16.
    float p  = s * (1.0f / NT);
    float c0 = low ? p * Wd[j * NC + 0] : 0.f;
    float c1 = low ? p * Wd[j * NC + 1] : 0.f;
    #pragma unroll
    for (int off = 16; off; off >>= 1) {
        c0 += __shfl_xor_sync(0xffffffffu, c0, off);
        c1 += __shfl_xor_sync(0xffffffffu, c1, off);
    }
    if (l == 0) { red[g][w][0] = c0; red[g][w][1] = c1; }
    bar_group(barid);
    if (gtid == 0) {
        float C0 = red[g][0][0] + red[g][1][0] + red[g][2][0] + red[g][3][0] + bd[0];
        float C1 = red[g][0][1] + red[g][1][1] + red[g][2][1] + red[g][3][1] + bd[1];
        out[b * NC + 0] = 1.0f / (1.0f + expf(-C0));
        out[b * NC + 1] = 1.0f / (1.0f + expf(-C1));
    }
}

// ---------------------------------------------------------------------------
extern "C" void kernel_launch(void* const* d_in, const int* in_sizes, int n_in,
                              void* d_out, int out_size) {
    const int*   tokens = (const int*)  d_in[0];
    const float* E      = (const float*)d_in[1];
    const float* W      = (const float*)d_in[2];
    const float* U      = (const float*)d_in[3];
    const float* bias   = (const float*)d_in[4];
    const float* Wd     = (const float*)d_in[5];
    const float* bd     = (const float*)d_in[6];
    float* out = (float*)d_out;

    ew_kernel<<<(NV + 3) / 4, 256>>>(E, W, bias);
    rnn_kernel<<<NB / 4, 512>>>(tokens, U, Wd, bd, out);
}

// round 12
// speedup vs baseline: 1.1702x; 1.1702x over previous
#include <cuda_runtime.h>

#define NB 256
#define NT 1024
#define NV 5000
#define ND 100
#define NH 64
#define NC 2

// Scratch: EW = E @ W + b, [V, H]. 1.28 MB -> fully L2-resident.
__device__ float g_EWb[NV * NH];

// ---------------------------------------------------------------------------
// Kernel A: EWb[v][j] = sum_d E[v][d] * W[d][j] + b[j]
// ---------------------------------------------------------------------------
__global__ void ew_kernel(const float* __restrict__ E,
                          const float* __restrict__ W,
                          const float* __restrict__ bias) {
    int v = blockIdx.x * 4 + (threadIdx.x >> 6);
    int j = threadIdx.x & 63;
    if (v >= NV) return;
    float acc = bias[j];
    const float* e = E + v * ND;
    #pragma unroll 4
    for (int d = 0; d < ND; d++)
        acc = fmaf(e[d], W[d * NH + j], acc);
    g_EWb[v * NH + j] = acc;
}

// HW tanh (MUFU.TANH): lat 16, single instruction, ~2^-11 error.
__device__ __forceinline__ float tanh_fast(float x) {
    float y;
    asm("tanh.approx.f32 %0, %1;" : "=f"(y) : "f"(x));
    return y;
}

// Named barrier over a 128-thread subset (ids 1..2).
__device__ __forceinline__ void bar_group(int id) {
    asm volatile("bar.sync %0, 128;" :: "r"(id) : "memory");
}

// ---------------------------------------------------------------------------
// Kernel B: masked tanh RNN, T=1024 steps + mean-pool + dense + sigmoid.
// TWO ROWS PER BLOCK (256 threads = 8 warps = 2 groups x 4 warps),
// grid = 128 <= 148 SMs -> every block gets its own SM, ALL 256 rows
// resident, each SMSP interleaves 2 warps from 2 INDEPENDENT recurrences.
// R11 (4 rows/block, grid 64) proved scheduler-level interleave works
// (issue 63%, ~63us/row per SM) but used only 64 SMs; this keeps the
// interleave and restores full chip coverage. Each group runs the proven
// R4 machinery VERBATIM: K-split by 2 in-warp, lanes (l, l+16) of group-
// warp w own output j = 16w + (l&15), 32 scalar FFMA + 8 LDS.128 per
// thread, one shfl.bfly(16) merge, ptxas-scheduled unroll-2 ping-pong.
// Groups sync on their OWN named barrier so they drift freely and cover
// each other's latency stalls.
// ---------------------------------------------------------------------------
__global__ void __launch_bounds__(256) rnn_kernel(
    const int* __restrict__ tokens,
    const float* __restrict__ U,
    const float* __restrict__ Wd,
    const float* __restrict__ bd,
    float* __restrict__ out)
{
    __shared__ __align__(16) float hbuf[2][2][NH];
    __shared__ float red[2][4][2];
    const int g     = threadIdx.x >> 7;        // row group 0..1
    const int gtid  = threadIdx.x & 127;       // tid within group
    const int w     = gtid >> 5;               // warp within group
    const int l     = threadIdx.x & 31;
    const int j     = w * 16 + (l & 15);
    const int kbase = (l >> 4) * 32;
    const bool low  = (l < 16);
    const int barid = 1 + g;
    const int b     = blockIdx.x * 2 + g;      // this group's batch row

    // U[kbase..kbase+31][j] in 32 registers.
    float Ucol[NH / 2];
    #pragma unroll
    for (int k = 0; k < NH / 2; k++)
        Ucol[k] = U[(kbase + k) * NH + j];

    if (gtid < NH) hbuf[g][0][gtid] = 0.f;
    __syncthreads();   // one full-block barrier covers both groups' init

    const int* trow = tokens + b * NT;
    float h = 0.f, s = 0.f;

    // Pipeline: tokens 3 ahead, EW rows 2 ahead (2 steps >= L2 ~234cyc).
    int tok0 = trow[0];
    int tok1 = trow[1];
    int tok2 = trow[2];
    float ew0 = g_EWb[tok0 * NH + j];
    float ew1 = g_EWb[tok1 * NH + j];

    #pragma unroll 2
    for (int t = 0; t < NT; t++) {
        int t3 = (t + 3 < NT) ? (t + 3) : (NT - 1);
        int tok3 = trow[t3];
        float ew2 = g_EWb[tok2 * NH + j];

        // Partial dot: sum_{k in half} h[k] * U[k][j].  8 broadcast LDS.128.
        const float4* hp = reinterpret_cast<const float4*>(hbuf[g][t & 1] + kbase);
        float4 h0 = hp[0], h1 = hp[1], h2 = hp[2], h3 = hp[3];
        float4 h4 = hp[4], h5 = hp[5], h6 = hp[6], h7 = hp[7];
        float a0 = 0.f, a1 = 0.f, a2 = 0.f, a3 = 0.f;
        float a4 = 0.f, a5 = 0.f, a6 = 0.f, a7 = 0.f;
        a0 = fmaf(h0.x, Ucol[0],  a0);  a1 = fmaf(h0.y, Ucol[1],  a1);
        a2 = fmaf(h0.z, Ucol[2],  a2);  a3 = fmaf(h0.w, Ucol[3],  a3);
        a4 = fmaf(h1.x, Ucol[4],  a4);  a5 = fmaf(h1.y, Ucol[5],  a5);
        a6 = fmaf(h1.z, Ucol[6],  a6);  a7 = fmaf(h1.w, Ucol[7],  a7);
        a0 = fmaf(h2.x, Ucol[8],  a0);  a1 = fmaf(h2.y, Ucol[9],  a1);
        a2 = fmaf(h2.z, Ucol[10], a2);  a3 = fmaf(h2.w, Ucol[11], a3);
        a4 = fmaf(h3.x, Ucol[12], a4);  a5 = fmaf(h3.y, Ucol[13], a5);
        a6 = fmaf(h3.z, Ucol[14], a6);  a7 = fmaf(h3.w, Ucol[15], a7);
        a0 = fmaf(h4.x, Ucol[16], a0);  a1 = fmaf(h4.y, Ucol[17], a1);
        a2 = fmaf(h4.z, Ucol[18], a2);  a3 = fmaf(h4.w, Ucol[19], a3);
        a4 = fmaf(h5.x, Ucol[20], a4);  a5 = fmaf(h5.y, Ucol[21], a5);
        a6 = fmaf(h5.z, Ucol[22], a6);  a7 = fmaf(h5.w, Ucol[23], a7);
        a0 = fmaf(h6.x, Ucol[24], a0);  a1 = fmaf(h6.y, Ucol[25], a1);
        a2 = fmaf(h6.z, Ucol[26], a2);  a3 = fmaf(h6.w, Ucol[27], a3);
        a4 = fmaf(h7.x, Ucol[28], a4);  a5 = fmaf(h7.y, Ucol[29], a5);
        a6 = fmaf(h7.z, Ucol[30], a6);  a7 = fmaf(h7.w, Ucol[31], a7);
        float p = ((a0 + a1) + (a2 + a3)) + ((a4 + a5) + (a6 + a7));
        // Merge K-halves: partner lane is l^16, same warp.
        float a = p + __shfl_xor_sync(0xffffffffu, p, 16) + ew0;
        float hn = tanh_fast(a);

        // Masked recurrence: token 0 carries previous state (group-uniform).
        if (tok0 != 0) h = hn;
        s += h;

        // Publish into the other buffer (one writer per output).
        if (low) hbuf[g][(t & 1) ^ 1][j] = h;
        bar_group(barid);

        tok0 = tok1; tok1 = tok2; tok2 = tok3;
        ew0 = ew1;  ew1 = ew2;
    }

    // Epilogue: mean pool -> dense (64 -> 2) -> sigmoid, per group.
    // Output j is held by 2 lanes; count only l<16.
    float p  = s * (1.0f / NT);
    float c0 = low ? p * Wd[j * NC + 0] : 0.f;
    float c1 = low ? p * Wd[j * NC + 1] : 0.f;
    #pragma unroll
    for (int off = 16; off; off >>= 1) {
        c0 += __shfl_xor_sync(0xffffffffu, c0, off);
        c1 += __shfl_xor_sync(0xffffffffu, c1, off);
    }
    if (l == 0) { red[g][w][0] = c0; red[g][w][1] = c1; }
    bar_group(barid);
    if (gtid == 0) {
        float C0 = red[g][0][0] + red[g][1][0] + red[g][2][0] + red[g][3][0] + bd[0];
        float C1 = red[g][0][1] + red[g][1][1] + red[g][2][1] + red[g][3][1] + bd[1];
        out[b * NC + 0] = 1.0f / (1.0f + expf(-C0));
        out[b * NC + 1] = 1.0f / (1.0f + expf(-C1));
    }
}

// ---------------------------------------------------------------------------
extern "C" void kernel_launch(void* const* d_in, const int* in_sizes, int n_in,
                              void* d_out, int out_size) {
    const int*   tokens = (const int*)  d_in[0];
    const float* E      = (const float*)d_in[1];
    const float* W      = (const float*)d_in[2];
    const float* U      = (const float*)d_in[3];
    const float* bias   = (const float*)d_in[4];
    const float* Wd     = (const float*)d_in[5];
    const float* bd     = (const float*)d_in[6];
    float* out = (float*)d_out;

    ew_kernel<<<(NV + 3) / 4, 256>>>(E, W, bias);
    rnn_kernel<<<NB / 2, 256>>>(tokens, U, Wd, bd, out);
}

// round 14
// speedup vs baseline: 1.7046x; 1.4566x over previous
#include <cuda_runtime.h>
#include <cuda_fp16.h>

#define NB 256
#define NT 1024
#define NV 5000
#define ND 100
#define NH 64
#define NC 2

// Scratch: EW = E @ W + b, [V, H]. 1.28 MB -> fully L2-resident.
__device__ float g_EWb[NV * NH];

// ---------------------------------------------------------------------------
// Kernel A: EWb[v][j] = sum_d E[v][d] * W[d][j] + b[j]
// ---------------------------------------------------------------------------
__global__ void ew_kernel(const float* __restrict__ E,
                          const float* __restrict__ W,
                          const float* __restrict__ bias) {
    int v = blockIdx.x * 4 + (threadIdx.x >> 6);
    int j = threadIdx.x & 63;
    if (v >= NV) return;
    float acc = bias[j];
    const float* e = E + v * ND;
    #pragma unroll 4
    for (int d = 0; d < ND; d++)
        acc = fmaf(e[d], W[d * NH + j], acc);
    g_EWb[v * NH + j] = acc;
}

// HW tanh (MUFU.TANH): lat 16, single instruction, ~2^-11 error.
__device__ __forceinline__ float tanh_fast(float x) {
    float y;
    asm("tanh.approx.f32 %0, %1;" : "=f"(y) : "f"(x));
    return y;
}

// 16-byte chunk of 4 half2 (8 h-values) -> one LDS.128.
struct __align__(16) H2x4 { __half2 a, b, c, d; };

// ---------------------------------------------------------------------------
// Kernel B: masked tanh RNN, T=1024 steps + mean-pool + dense + sigmoid.
// STRUCTURE = R4 (best, 166us; placement optimum: 256 blocks x 128 thr,
// 2 blocks/SM on loaded SMs -> 2 independent recurrences per SMSP with
// cheap per-block __syncthreads and free drift). R13 delta: the h@U dot
// runs in PACKED FP16 (HFMA2): lane's 32-k half becomes 16 __hfma2 into
// 8 half2 accumulators + 7 __hadd2 tree, h exchanged through smem as
// halves (4x LDS.128 instead of 8). Everything else fp32: ew add, tanh,
// h carry, mean-pool, epilogue. FMA-pipe issue per step drops ~80->~50
// cyc and LDS bytes halve; fp16 accumulation error (~4e-4/step) is the
// same order as tanh.approx error, which measured 7e-8 at the output.
// ---------------------------------------------------------------------------
__global__ void __launch_bounds__(128) rnn_kernel(
    const int* __restrict__ tokens,
    const float* __restrict__ U,
    const float* __restrict__ Wd,
    const float* __restrict__ bd,
    float* __restrict__ out)
{
    __shared__ __align__(16) __half hbuf[2][NH];
    __shared__ float red[4][2];
    const int w     = threadIdx.x >> 5;
    const int l     = threadIdx.x & 31;
    const int j     = w * 16 + (l & 15);
    const int kbase = (l >> 4) * 32;       // this lane's K-half (in halves)
    const bool low  = (l < 16);
    const int b     = blockIdx.x;

    // U K-pairs for this lane's half, packed half2 in natural memory order:
    // Upk[m] = (U[kbase+2m][j], U[kbase+2m+1][j]).
    __half2 Upk[16];
    #pragma unroll
    for (int m = 0; m < 16; m++) {
        float ua = U[(kbase + 2 * m)     * NH + j];
        float ub = U[(kbase + 2 * m + 1) * NH + j];
        Upk[m] = __floats2half2_rn(ua, ub);
    }

    if (threadIdx.x < NH) hbuf[0][threadIdx.x] = __float2half(0.f);
    __syncthreads();

    const int* trow = tokens + b * NT;
    float h = 0.f, s = 0.f;

    // Pipeline: tokens 3 ahead, EW rows 2 ahead (2 steps >= L2 ~234cyc).
    int tok0 = trow[0];
    int tok1 = trow[1];
    int tok2 = trow[2];
    float ew0 = g_EWb[tok0 * NH + j];
    float ew1 = g_EWb[tok1 * NH + j];

    #pragma unroll 2
    for (int t = 0; t < NT; t++) {
        int t3 = (t + 3 < NT) ? (t + 3) : (NT - 1);
        int tok3 = trow[t3];
        float ew2 = g_EWb[tok2 * NH + j];

        // Partial dot over this lane's K-half, packed fp16. 4x LDS.128.
        const H2x4* hp = reinterpret_cast<const H2x4*>(hbuf[t & 1] + kbase);
        H2x4 v0 = hp[0], v1 = hp[1], v2 = hp[2], v3 = hp[3];
        __half2 z  = __float2half2_rn(0.f);
        __half2 A0 = z, A1 = z, A2 = z, A3 = z;
        __half2 A4 = z, A5 = z, A6 = z, A7 = z;
        A0 = __hfma2(v0.a, Upk[0],  A0);  A1 = __hfma2(v0.b, Upk[1],  A1);
        A2 = __hfma2(v0.c, Upk[2],  A2);  A3 = __hfma2(v0.d, Upk[3],  A3);
        A4 = __hfma2(v1.a, Upk[4],  A4);  A5 = __hfma2(v1.b, Upk[5],  A5);
        A6 = __hfma2(v1.c, Upk[6],  A6);  A7 = __hfma2(v1.d, Upk[7],  A7);
        A0 = __hfma2(v2.a, Upk[8],  A0);  A1 = __hfma2(v2.b, Upk[9],  A1);
        A2 = __hfma2(v2.c, Upk[10], A2);  A3 = __hfma2(v2.d, Upk[11], A3);
        A4 = __hfma2(v3.a, Upk[12], A4);  A5 = __hfma2(v3.b, Upk[13], A5);
        A6 = __hfma2(v3.c, Upk[14], A6);  A7 = __hfma2(v3.d, Upk[15], A7);
        __half2 B0 = __hadd2(A0, A1), B1 = __hadd2(A2, A3);
        __half2 B2 = __hadd2(A4, A5), B3 = __hadd2(A6, A7);
        __half2 C0 = __hadd2(B0, B1), C1 = __hadd2(B2, B3);
        __half2 D  = __hadd2(C0, C1);
        float2 f   = __half22float2(D);
        float p    = f.x + f.y;
        // Merge K-halves: partner lane is l^16, same warp.
        float a = p + __shfl_xor_sync(0xffffffffu, p, 16) + ew0;
        float hn = tanh_fast(a);

        // Masked recurrence: token 0 carries previous state (block-uniform).
        if (tok0 != 0) h = hn;
        s += h;

        // Publish into the other buffer (one writer per output).
        if (low) hbuf[(t & 1) ^ 1][j] = __float2half(h);
        __syncthreads();

        tok0 = tok1; tok1 = tok2; tok2 = tok3;
        ew0 = ew1;  ew1 = ew2;
    }

    // Epilogue: mean pool -> dense (64 -> 2) -> sigmoid. Output j is held by
    // 2 lanes; count only l<16.
    float p  = s * (1.0f / NT);
    float c0 = low ? p * Wd[j * NC + 0] : 0.f;
    float c1 = low ? p * Wd[j * NC + 1] : 0.f;
    #pragma unroll
    for (int off = 16; off; off >>= 1) {
        c0 += __shfl_xor_sync(0xffffffffu, c0, off);
        c1 += __shfl_xor_sync(0xffffffffu, c1, off);
    }
    if (l == 0) { red[w][0] = c0; red[w][1] = c1; }
    __syncthreads();
    if (threadIdx.x == 0) {
        float C0 = red[0][0] + red[1][0] + red[2][0] + red[3][0] + bd[0];
        float C1 = red[0][1] + red[1][1] + red[2][1] + red[3][1] + bd[1];
        out[b * NC + 0] = 1.0f / (1.0f + expf(-C0));
        out[b * NC + 1] = 1.0f / (1.0f + expf(-C1));
    }
}

// ---------------------------------------------------------------------------
extern "C" void kernel_launch(void* const* d_in, const int* in_sizes, int n_in,
                              void* d_out, int out_size) {
    const int*   tokens = (const int*)  d_in[0];
    const float* E      = (const float*)d_in[1];
    const float* W      = (const float*)d_in[2];
    const float* U      = (const float*)d_in[3];
    const float* bias   = (const float*)d_in[4];
    const float* Wd     = (const float*)d_in[5];
    const float* bd     = (const float*)d_in[6];
    float* out = (float*)d_out;

    ew_kernel<<<(NV + 3) / 4, 256>>>(E, W, bias);
    rnn_kernel<<<NB, 128>>>(tokens, U, Wd, bd, out);
}